// round 1
// baseline (speedup 1.0000x reference)
#include <cuda_runtime.h>

#define NTH 256
#define NEG 0.2f

// ---- dynamic SMEM layout (float offsets) ----
// Region A [0, 32768): voxel during stage0/1; then buf2 (8*512=4096) at +0,
//                      w4 (13824) at +4096; later w5 chunk (27648) at +0.
// Region B [32768, 49152): buf1 (4*4096 = 16384)
// Region C [49152, ...): small weights + buf3 + buf4 + feat + head scratch
#define A_OFF    0
#define B_OFF    32768
#define C_OFF    49152
#define W1_OFF   (C_OFF)          // 108
#define B1_OFF   (C_OFF + 108)    // 4
#define W2_OFF   (C_OFF + 112)    // 864
#define B2_OFF   (C_OFF + 976)    // 8
#define W3_OFF   (C_OFF + 984)    // 3456
#define B3_OFF   (C_OFF + 4440)   // 16
#define BUF3_OFF (C_OFF + 4456)   // 1024 (16 ch * 4^3)  ... reused as head scratch later
#define BUF4_OFF (C_OFF + 5480)   // 256  (32 ch * 2^3)
#define FEAT_OFF (C_OFF + 5736)   // 64
#define SMEM_FLOATS (C_OFF + 5800)

__device__ __forceinline__ float lrelu(float x) { return x >= 0.0f ? x : NEG * x; }

extern __shared__ float smem[];

__global__ __launch_bounds__(NTH, 1)
void prs_net_kernel(const float* __restrict__ vox,
                    const float* __restrict__ w1, const float* __restrict__ b1,
                    const float* __restrict__ w2, const float* __restrict__ b2,
                    const float* __restrict__ w3, const float* __restrict__ b3,
                    const float* __restrict__ w4, const float* __restrict__ b4,
                    const float* __restrict__ w5, const float* __restrict__ b5,
                    const float* __restrict__ hW1, const float* __restrict__ hb1,
                    const float* __restrict__ hW2, const float* __restrict__ hb2,
                    const float* __restrict__ hW3, const float* __restrict__ hb3,
                    float* __restrict__ out)
{
    const int tid = threadIdx.x;
    const int b   = blockIdx.x;
    float* sA = smem + A_OFF;
    float* sB = smem + B_OFF;

    // ---------------- stage 0: load voxel (32^3) + small weights ----------------
    {
        const float4* v4 = (const float4*)(vox + (size_t)b * 32768);
        float4* a4 = (float4*)sA;
        for (int i = tid; i < 8192; i += NTH) a4[i] = v4[i];
        for (int i = tid; i < 108; i += NTH)  smem[W1_OFF + i] = w1[i];
        if (tid < 4)                          smem[B1_OFF + tid] = b1[tid];
        for (int i = tid; i < 864; i += NTH)  smem[W2_OFF + i] = w2[i];
        if (tid < 8)                          smem[B2_OFF + tid] = b2[tid];
        for (int i = tid; i < 3456; i += NTH) smem[W3_OFF + i] = w3[i];
        if (tid < 16)                         smem[B3_OFF + tid] = b3[tid];
    }
    __syncthreads();

    // ---------------- stage 1: conv1 (1->4) @32^3 + pool -> buf1 [4][16^3] -------
    for (int c = tid; c < 4096; c += NTH) {
        const int px = c & 15, py = (c >> 4) & 15, pz = c >> 8;
        const int bx = 2 * px - 1, by = 2 * py - 1, bz = 2 * pz - 1;
        float p[64];
        #pragma unroll
        for (int dz = 0; dz < 4; dz++) {
            const int z = bz + dz; const bool zok = (unsigned)z < 32u;
            #pragma unroll
            for (int dy = 0; dy < 4; dy++) {
                const int y = by + dy; const bool yok = (unsigned)y < 32u;
                const float* row = sA + (z * 32 + y) * 32;
                #pragma unroll
                for (int dx = 0; dx < 4; dx++) {
                    const int x = bx + dx;
                    p[(dz * 4 + dy) * 4 + dx] =
                        (zok && yok && (unsigned)x < 32u) ? row[x] : 0.0f;
                }
            }
        }
        #pragma unroll
        for (int oc = 0; oc < 4; oc++) {
            float acc[8];
            #pragma unroll
            for (int j = 0; j < 8; j++) acc[j] = 0.0f;
            const float* wp = smem + W1_OFF + oc * 27;
            #pragma unroll
            for (int kd = 0; kd < 3; kd++)
            #pragma unroll
            for (int kh = 0; kh < 3; kh++)
            #pragma unroll
            for (int kw = 0; kw < 3; kw++) {
                const float w = wp[(kd * 3 + kh) * 3 + kw];
                #pragma unroll
                for (int j = 0; j < 8; j++) {
                    const int jz = (j >> 2) & 1, jy = (j >> 1) & 1, jx = j & 1;
                    acc[j] += w * p[((jz + kd) * 4 + jy + kh) * 4 + jx + kw];
                }
            }
            float m = acc[0];
            #pragma unroll
            for (int j = 1; j < 8; j++) m = fmaxf(m, acc[j]);
            sB[oc * 4096 + c] = lrelu(m + smem[B1_OFF + oc]);
        }
    }
    __syncthreads();   // voxel region A is now free

    // ---------------- stage 2: conv2 (4->8) @16^3 + pool -> buf2 [8][8^3] @A ----
    // also stage w4 into A+4096 (A is free; buf2 only uses A[0..4096))
    {
        const float4* s4 = (const float4*)w4;
        float4* d4 = (float4*)(sA + 4096);
        for (int i = tid; i < 3456; i += NTH) d4[i] = s4[i];
    }
    for (int it = tid; it < 2048; it += NTH) {
        const int cell = it & 511, og = it >> 9;      // og picks oc pair {2og, 2og+1}
        const int px = cell & 7, py = (cell >> 3) & 7, pz = cell >> 6;
        const int bx = 2 * px - 1, by = 2 * py - 1, bz = 2 * pz - 1;
        float acc0[8], acc1[8];
        #pragma unroll
        for (int j = 0; j < 8; j++) { acc0[j] = 0.0f; acc1[j] = 0.0f; }
        #pragma unroll 1
        for (int ic = 0; ic < 4; ic++) {
            const float* xin = sB + ic * 4096;
            float p[64];
            #pragma unroll
            for (int dz = 0; dz < 4; dz++) {
                const int z = bz + dz; const bool zok = (unsigned)z < 16u;
                #pragma unroll
                for (int dy = 0; dy < 4; dy++) {
                    const int y = by + dy; const bool yok = (unsigned)y < 16u;
                    const float* row = xin + (z * 16 + y) * 16;
                    #pragma unroll
                    for (int dx = 0; dx < 4; dx++) {
                        const int x = bx + dx;
                        p[(dz * 4 + dy) * 4 + dx] =
                            (zok && yok && (unsigned)x < 16u) ? row[x] : 0.0f;
                    }
                }
            }
            const float* w0 = smem + W2_OFF + ((2 * og) * 4 + ic) * 27;
            const float* w1p = w0 + 4 * 27;
            #pragma unroll
            for (int kd = 0; kd < 3; kd++)
            #pragma unroll
            for (int kh = 0; kh < 3; kh++)
            #pragma unroll
            for (int kw = 0; kw < 3; kw++) {
                const int t = (kd * 3 + kh) * 3 + kw;
                const float wa = w0[t], wb = w1p[t];
                #pragma unroll
                for (int j = 0; j < 8; j++) {
                    const int jz = (j >> 2) & 1, jy = (j >> 1) & 1, jx = j & 1;
                    const float v = p[((jz + kd) * 4 + jy + kh) * 4 + jx + kw];
                    acc0[j] += wa * v;
                    acc1[j] += wb * v;
                }
            }
        }
        #pragma unroll
        for (int u = 0; u < 2; u++) {
            float* acc = u ? acc1 : acc0;
            float m = acc[0];
            #pragma unroll
            for (int j = 1; j < 8; j++) m = fmaxf(m, acc[j]);
            const int oc = 2 * og + u;
            sA[oc * 512 + cell] = lrelu(m + smem[B2_OFF + oc]);
        }
    }
    __syncthreads();

    // ---------------- stage 3: conv3 (8->16) @8^3 + pool -> buf3 [16][4^3] ------
    for (int it = tid; it < 1024; it += NTH) {
        const int oc = it >> 6, cell = it & 63;
        const int px = cell & 3, py = (cell >> 2) & 3, pz = (cell >> 4) & 3;
        const int bx = 2 * px - 1, by = 2 * py - 1, bz = 2 * pz - 1;
        float acc[8];
        #pragma unroll
        for (int j = 0; j < 8; j++) acc[j] = 0.0f;
        #pragma unroll 1
        for (int ic = 0; ic < 8; ic++) {
            const float* xin = sA + ic * 512;
            float p[64];
            #pragma unroll
            for (int dz = 0; dz < 4; dz++) {
                const int z = bz + dz; const bool zok = (unsigned)z < 8u;
                #pragma unroll
                for (int dy = 0; dy < 4; dy++) {
                    const int y = by + dy; const bool yok = (unsigned)y < 8u;
                    const float* row = xin + (z * 8 + y) * 8;
                    #pragma unroll
                    for (int dx = 0; dx < 4; dx++) {
                        const int x = bx + dx;
                        p[(dz * 4 + dy) * 4 + dx] =
                            (zok && yok && (unsigned)x < 8u) ? row[x] : 0.0f;
                    }
                }
            }
            const float* wp = smem + W3_OFF + (oc * 8 + ic) * 27;
            #pragma unroll
            for (int kd = 0; kd < 3; kd++)
            #pragma unroll
            for (int kh = 0; kh < 3; kh++)
            #pragma unroll
            for (int kw = 0; kw < 3; kw++) {
                const float w = wp[(kd * 3 + kh) * 3 + kw];
                #pragma unroll
                for (int j = 0; j < 8; j++) {
                    const int jz = (j >> 2) & 1, jy = (j >> 1) & 1, jx = j & 1;
                    acc[j] += w * p[((jz + kd) * 4 + jy + kh) * 4 + jx + kw];
                }
            }
        }
        float m = acc[0];
        #pragma unroll
        for (int j = 1; j < 8; j++) m = fmaxf(m, acc[j]);
        smem[BUF3_OFF + oc * 64 + cell] = lrelu(m + smem[B3_OFF + oc]);
    }
    __syncthreads();

    // ---------------- stage 4: conv4 (16->32) @4^3 + pool -> buf4 [32][2^3] -----
    {
        const int oc = tid >> 3, cell = tid & 7;
        const int px = cell & 1, py = (cell >> 1) & 1, pz = (cell >> 2) & 1;
        const int bx = 2 * px - 1, by = 2 * py - 1, bz = 2 * pz - 1;
        float acc[8];
        #pragma unroll
        for (int j = 0; j < 8; j++) acc[j] = 0.0f;
        const float* wbase = sA + 4096 + oc * 16 * 27;
        #pragma unroll 1
        for (int ic = 0; ic < 16; ic++) {
            const float* xin = smem + BUF3_OFF + ic * 64;
            float p[64];
            #pragma unroll
            for (int dz = 0; dz < 4; dz++) {
                const int z = bz + dz; const bool zok = (unsigned)z < 4u;
                #pragma unroll
                for (int dy = 0; dy < 4; dy++) {
                    const int y = by + dy; const bool yok = (unsigned)y < 4u;
                    const float* row = xin + (z * 4 + y) * 4;
                    #pragma unroll
                    for (int dx = 0; dx < 4; dx++) {
                        const int x = bx + dx;
                        p[(dz * 4 + dy) * 4 + dx] =
                            (zok && yok && (unsigned)x < 4u) ? row[x] : 0.0f;
                    }
                }
            }
            const float* wp = wbase + ic * 27;
            #pragma unroll
            for (int kd = 0; kd < 3; kd++)
            #pragma unroll
            for (int kh = 0; kh < 3; kh++)
            #pragma unroll
            for (int kw = 0; kw < 3; kw++) {
                const float w = wp[(kd * 3 + kh) * 3 + kw];
                #pragma unroll
                for (int j = 0; j < 8; j++) {
                    const int jz = (j >> 2) & 1, jy = (j >> 1) & 1, jx = j & 1;
                    acc[j] += w * p[((jz + kd) * 4 + jy + kh) * 4 + jx + kw];
                }
            }
        }
        float m = acc[0];
        #pragma unroll
        for (int j = 1; j < 8; j++) m = fmaxf(m, acc[j]);
        smem[BUF4_OFF + oc * 8 + cell] = lrelu(m + __ldg(&b4[oc]));
    }
    __syncthreads();

    // ---------------- stage 5: conv5 (32->64) @2^3 + pool -> feat[64] -----------
    // two 32-oc chunks; each chunk stages 32*32*27 w5 floats into A
    #pragma unroll 1
    for (int g = 0; g < 2; g++) {
        {
            const float4* s4 = (const float4*)(w5 + g * 27648);
            float4* d4 = (float4*)sA;
            for (int i = tid; i < 6912; i += NTH) d4[i] = s4[i];
        }
        __syncthreads();
        const int ocl = tid >> 3, cell = tid & 7;
        const int dx = cell & 1, dy = (cell >> 1) & 1, dz = (cell >> 2) & 1;
        const float* wbase = sA + ocl * 32 * 27;
        float acc = 0.0f;
        #pragma unroll 4
        for (int ic = 0; ic < 32; ic++) {
            const float* wp  = wbase + ic * 27;
            const float* xin = smem + BUF4_OFF + ic * 8;
            #pragma unroll
            for (int jz = 0; jz < 2; jz++)
            #pragma unroll
            for (int jy = 0; jy < 2; jy++)
            #pragma unroll
            for (int jx = 0; jx < 2; jx++) {
                acc += xin[(jz * 2 + jy) * 2 + jx] *
                       wp[((1 - dz + jz) * 3 + (1 - dy + jy)) * 3 + (1 - dx + jx)];
            }
        }
        #pragma unroll
        for (int m = 1; m < 8; m <<= 1)
            acc = fmaxf(acc, __shfl_xor_sync(0xffffffffu, acc, m));
        if (cell == 0) {
            const int oc = g * 32 + ocl;
            smem[FEAT_OFF + oc] = lrelu(acc + __ldg(&b5[oc]));
        }
        __syncthreads();
    }

    // ---------------- heads: [64]->[6,32]->[6,16]->[6,4] -> normalize -----------
    if (tid < 192) {                                   // layer 1
        const int h = tid >> 5, o = tid & 31;
        float acc = __ldg(&hb1[h * 32 + o]);
        const float* Wp = hW1 + (h * 64) * 32 + o;
        #pragma unroll
        for (int f = 0; f < 64; f++) acc += smem[FEAT_OFF + f] * __ldg(&Wp[f * 32]);
        smem[BUF3_OFF + tid] = lrelu(acc);
    }
    __syncthreads();
    if (tid < 96) {                                    // layer 2
        const int h = tid >> 4, o = tid & 15;
        float acc = __ldg(&hb2[h * 16 + o]);
        const float* Wp  = hW2 + (h * 32) * 16 + o;
        const float* hin = smem + BUF3_OFF + h * 32;
        #pragma unroll
        for (int f = 0; f < 32; f++) acc += hin[f] * __ldg(&Wp[f * 16]);
        smem[BUF3_OFF + 192 + tid] = lrelu(acc);
    }
    __syncthreads();
    if (tid < 24) {                                    // layer 3
        const int h = tid >> 2, o = tid & 3;
        float acc = __ldg(&hb3[h * 4 + o]);
        const float* Wp  = hW3 + (h * 16) * 4 + o;
        const float* hin = smem + BUF3_OFF + 192 + h * 16;
        #pragma unroll
        for (int f = 0; f < 16; f++) acc += hin[f] * __ldg(&Wp[f * 4]);
        smem[BUF3_OFF + 288 + tid] = lrelu(acc);
    }
    __syncthreads();
    if (tid < 24) {                                    // unitize over last dim (4)
        const int h = tid >> 2;
        const float* hv = smem + BUF3_OFF + 288 + h * 4;
        const float n = rsqrtf(hv[0] * hv[0] + hv[1] * hv[1] +
                               hv[2] * hv[2] + hv[3] * hv[3]);
        out[(size_t)b * 24 + tid] = smem[BUF3_OFF + 288 + tid] * n;
    }
}

extern "C" void kernel_launch(void* const* d_in, const int* in_sizes, int n_in,
                              void* d_out, int out_size)
{
    const int B = in_sizes[0] / 32768;                 // 1024
    const size_t smem_bytes = (size_t)SMEM_FLOATS * sizeof(float);  // 219808 B
    cudaFuncSetAttribute(prs_net_kernel,
                         cudaFuncAttributeMaxDynamicSharedMemorySize,
                         (int)smem_bytes);
    prs_net_kernel<<<B, NTH, smem_bytes>>>(
        (const float*)d_in[0],
        (const float*)d_in[1],  (const float*)d_in[2],
        (const float*)d_in[3],  (const float*)d_in[4],
        (const float*)d_in[5],  (const float*)d_in[6],
        (const float*)d_in[7],  (const float*)d_in[8],
        (const float*)d_in[9],  (const float*)d_in[10],
        (const float*)d_in[11], (const float*)d_in[12],
        (const float*)d_in[13], (const float*)d_in[14],
        (const float*)d_in[15], (const float*)d_in[16],
        (float*)d_out);
}

// round 2
// speedup vs baseline: 1.3264x; 1.3264x over previous
#include <cuda_runtime.h>

#define NTH 512
#define NEG 0.2f

typedef unsigned long long ull;

// ---- dynamic SMEM layout (float offsets) ----
// Region A [0, 32768): voxel during stage0/1; then buf2 (8*512=4096) at +0 and
//                      packed w4 (13824) at +4096; later packed-w5 chunk (27648) at +0.
// Region B [32768, 49152): buf1 (4*4096) during stages 1-2; reduction scratch later.
// Region C [49152, ...): packed small weights + biases + buf3 + buf4 + feat + head scratch
#define A_OFF    0
#define B_OFF    32768
#define C_OFF    49152
#define W1P_OFF  (C_OFF)           // 108 floats (54 f2 pairs)
#define B1_OFF   (C_OFF + 108)     // 4
#define B2_OFF   (C_OFF + 112)     // 8
#define B3_OFF   (C_OFF + 120)     // 16
#define W2P_OFF  (C_OFF + 136)     // 864 (432 f2)
#define W3P_OFF  (C_OFF + 1000)    // 3456 (1728 f2)
#define BUF3_OFF (C_OFF + 4456)    // 1024 (16ch * 4^3)
#define BUF4_OFF (C_OFF + 5480)    // 256  (32ch * 2^3)
#define FEAT_OFF (C_OFF + 5736)    // 64
#define HSCR_OFF (C_OFF + 5800)    // 320 head scratch
#define SMEM_FLOATS (C_OFF + 6120) // 55272 floats = 221088 B

__device__ __forceinline__ float lrelu(float x) { return x >= 0.0f ? x : NEG * x; }

// pack {v, v} into a 64-bit f32x2 carrier (ALU pipe)
__device__ __forceinline__ ull dup2(float v) {
    ull d;
    asm("mov.b64 %0, {%1, %1};" : "=l"(d) : "f"(v));
    return d;
}
// packed dual FMA: acc = {a.lo*b.lo+acc.lo, a.hi*b.hi+acc.hi}
__device__ __forceinline__ void ffma2(ull& acc, ull a, ull b) {
    asm("fma.rn.f32x2 %0, %1, %2, %0;" : "+l"(acc) : "l"(a), "l"(b));
}
__device__ __forceinline__ void unpk(ull d, float& lo, float& hi) {
    asm("mov.b64 {%0, %1}, %2;" : "=f"(lo), "=f"(hi) : "l"(d));
}

extern __shared__ float smem[];

// Load a 4x4x4 patch (pool cell + conv halo) from an N^3 channel plane using
// aligned float2 (LDS.64) loads: row span [2px-1, 2px+2] via f2 at e-2, e, e+2.
template <int N>
__device__ __forceinline__ void load_patch(const float* __restrict__ base,
                                           int px, int py, int pz, float* p) {
    const int by = 2 * py - 1, bz = 2 * pz - 1, e = 2 * px;
    const bool mok = (px >= 1);
    const bool rok = (2 * px + 2 < N);
    const float2 zz = make_float2(0.0f, 0.0f);
    #pragma unroll
    for (int dz = 0; dz < 4; dz++) {
        const int z = bz + dz; const bool zok = (unsigned)z < (unsigned)N;
        #pragma unroll
        for (int dy = 0; dy < 4; dy++) {
            const int y = by + dy;
            const bool ok = zok && ((unsigned)y < (unsigned)N);
            const float* row = base + (z * N + y) * N;
            const float2 m = (ok && mok) ? *(const float2*)(row + e - 2) : zz;
            const float2 c = ok           ? *(const float2*)(row + e)     : zz;
            const float2 r = (ok && rok) ? *(const float2*)(row + e + 2) : zz;
            float* q = p + (dz * 4 + dy) * 4;
            q[0] = m.y; q[1] = c.x; q[2] = c.y; q[3] = r.x;
        }
    }
}

// Accumulate 3^3 conv over a 4^3 patch for NPAIR packed oc-pairs x 8 pool positions.
// wbase[g*wstride + t] holds packed weight pair {w_oc0, w_oc1} for k-step t.
template <int NPAIR>
__device__ __forceinline__ void conv_acc(const float* p, const ull* __restrict__ wbase,
                                         int wstride, ull (&acc)[NPAIR][8]) {
    #pragma unroll
    for (int kd = 0; kd < 3; kd++)
    #pragma unroll
    for (int kh = 0; kh < 3; kh++)
    #pragma unroll
    for (int kw = 0; kw < 3; kw++) {
        const int t = (kd * 3 + kh) * 3 + kw;
        ull v[8];
        #pragma unroll
        for (int j = 0; j < 8; j++) {
            const int jz = (j >> 2) & 1, jy = (j >> 1) & 1, jx = j & 1;
            v[j] = dup2(p[((jz + kd) * 4 + jy + kh) * 4 + jx + kw]);
        }
        #pragma unroll
        for (int g = 0; g < NPAIR; g++) {
            const ull w = wbase[g * wstride + t];
            #pragma unroll
            for (int j = 0; j < 8; j++) ffma2(acc[g][j], w, v[j]);
        }
    }
}

__device__ __forceinline__ void finish_pair(const ull acc[8], float blo, float bhi,
                                            float& olo, float& ohi) {
    float mlo, mhi;
    unpk(acc[0], mlo, mhi);
    #pragma unroll
    for (int j = 1; j < 8; j++) {
        float lo, hi; unpk(acc[j], lo, hi);
        mlo = fmaxf(mlo, lo); mhi = fmaxf(mhi, hi);
    }
    olo = lrelu(mlo + blo); ohi = lrelu(mhi + bhi);
}

__global__ __launch_bounds__(NTH, 1)
void prs_net_kernel(const float* __restrict__ vox,
                    const float* __restrict__ w1, const float* __restrict__ b1,
                    const float* __restrict__ w2, const float* __restrict__ b2,
                    const float* __restrict__ w3, const float* __restrict__ b3,
                    const float* __restrict__ w4, const float* __restrict__ b4,
                    const float* __restrict__ w5, const float* __restrict__ b5,
                    const float* __restrict__ hW1, const float* __restrict__ hb1,
                    const float* __restrict__ hW2, const float* __restrict__ hb2,
                    const float* __restrict__ hW3, const float* __restrict__ hb3,
                    float* __restrict__ out)
{
    const int tid = threadIdx.x;
    const int b   = blockIdx.x;
    float* sA = smem + A_OFF;
    float* sB = smem + B_OFF;

    // ---------------- stage 0: load voxel + pack small weights as oc-pairs ------
    {
        const float4* v4 = (const float4*)(vox + (size_t)b * 32768);
        float4* a4 = (float4*)sA;
        for (int i = tid; i < 8192; i += NTH) a4[i] = v4[i];

        float2* w1d = (float2*)(smem + W1P_OFF);       // [2 pairs][27]
        for (int i = tid; i < 54; i += NTH) {
            const int g = i / 27, t = i % 27;
            w1d[i] = make_float2(w1[(2 * g) * 27 + t], w1[(2 * g + 1) * 27 + t]);
        }
        float2* w2d = (float2*)(smem + W2P_OFF);       // [4 pairs][4 ic][27]
        for (int i = tid; i < 432; i += NTH) {
            const int g = i / 108, rem = i % 108, ic = rem / 27, t = rem % 27;
            w2d[i] = make_float2(w2[((2 * g) * 4 + ic) * 27 + t],
                                 w2[((2 * g + 1) * 4 + ic) * 27 + t]);
        }
        float2* w3d = (float2*)(smem + W3P_OFF);       // [8 pairs][8 ic][27]
        for (int i = tid; i < 1728; i += NTH) {
            const int g = i / 216, rem = i % 216, ic = rem / 27, t = rem % 27;
            w3d[i] = make_float2(w3[((2 * g) * 8 + ic) * 27 + t],
                                 w3[((2 * g + 1) * 8 + ic) * 27 + t]);
        }
        if (tid < 4)  smem[B1_OFF + tid] = b1[tid];
        if (tid < 8)  smem[B2_OFF + tid] = b2[tid];
        if (tid < 16) smem[B3_OFF + tid] = b3[tid];
    }
    __syncthreads();

    // ---------------- stage 1: conv1 (1->4) @32^3 + pool -> buf1 [4][16^3] @B ----
    {
        const ull* w1u = (const ull*)(smem + W1P_OFF);
        #pragma unroll 1
        for (int c = tid; c < 4096; c += NTH) {
            const int px = c & 15, py = (c >> 4) & 15, pz = c >> 8;
            float p[64];
            load_patch<32>(sA, px, py, pz, p);
            ull acc[2][8];
            #pragma unroll
            for (int g = 0; g < 2; g++)
                #pragma unroll
                for (int j = 0; j < 8; j++) acc[g][j] = 0ull;
            conv_acc<2>(p, w1u, 27, acc);
            #pragma unroll
            for (int g = 0; g < 2; g++) {
                float olo, ohi;
                finish_pair(acc[g], smem[B1_OFF + 2 * g], smem[B1_OFF + 2 * g + 1],
                            olo, ohi);
                sB[(2 * g) * 4096 + c]     = olo;
                sB[(2 * g + 1) * 4096 + c] = ohi;
            }
        }
    }
    __syncthreads();   // voxel region A now free

    // ---------------- stage 2: conv2 (4->8) @16^3 + pool -> buf2 [8][8^3] @A ----
    {
        // pack w4 pairs into A+4096 while A is free (buf2 uses only A[0,4096))
        float2* w4d = (float2*)(sA + 4096);            // [16 pairs][16 ic][27]
        for (int i = tid; i < 6912; i += NTH) {
            const int g = i / 432, rem = i % 432, ic = rem / 27, t = rem % 27;
            w4d[i] = make_float2(w4[((2 * g) * 16 + ic) * 27 + t],
                                 w4[((2 * g + 1) * 16 + ic) * 27 + t]);
        }
        const ull* w2u = (const ull*)(smem + W2P_OFF);
        const int cell = tid;                          // 512 cells, 1 per thread
        const int px = cell & 7, py = (cell >> 3) & 7, pz = cell >> 6;
        #pragma unroll 1
        for (int pp = 0; pp < 2; pp++) {               // 2 passes x 2 oc-pairs
            ull acc[2][8];
            #pragma unroll
            for (int g = 0; g < 2; g++)
                #pragma unroll
                for (int j = 0; j < 8; j++) acc[g][j] = 0ull;
            #pragma unroll 1
            for (int ic = 0; ic < 4; ic++) {
                float p[64];
                load_patch<16>(sB + ic * 4096, px, py, pz, p);
                conv_acc<2>(p, w2u + ((pp * 2) * 4 + ic) * 27, 108, acc);
            }
            #pragma unroll
            for (int g = 0; g < 2; g++) {
                const int oc0 = (pp * 2 + g) * 2;
                float olo, ohi;
                finish_pair(acc[g], smem[B2_OFF + oc0], smem[B2_OFF + oc0 + 1],
                            olo, ohi);
                sA[oc0 * 512 + cell]       = olo;
                sA[(oc0 + 1) * 512 + cell] = ohi;
            }
        }
    }
    __syncthreads();

    // ---------------- stage 3: conv3 (8->16) @8^3 + pool -> buf3 [16][4^3] ------
    {
        const ull* w3u = (const ull*)(smem + W3P_OFF);
        const int g = tid >> 6, cell = tid & 63;       // 8 pairs x 64 cells
        const int px = cell & 3, py = (cell >> 2) & 3, pz = cell >> 4;
        ull acc[1][8];
        #pragma unroll
        for (int j = 0; j < 8; j++) acc[0][j] = 0ull;
        #pragma unroll 1
        for (int ic = 0; ic < 8; ic++) {
            float p[64];
            load_patch<8>(sA + ic * 512, px, py, pz, p);
            conv_acc<1>(p, w3u + (g * 8 + ic) * 27, 0, acc);
        }
        const int oc0 = 2 * g;
        float olo, ohi;
        finish_pair(acc[0], smem[B3_OFF + oc0], smem[B3_OFF + oc0 + 1], olo, ohi);
        smem[BUF3_OFF + oc0 * 64 + cell]       = olo;
        smem[BUF3_OFF + (oc0 + 1) * 64 + cell] = ohi;
    }
    __syncthreads();

    // ---------------- stage 4: conv4 (16->32) @4^3 + pool -> buf4 [32][2^3] -----
    // ic split 4 ways so all 512 threads work; partial sums reduced via B scratch
    {
        const ull* w4u = (const ull*)(sA + 4096);
        const int icg = tid >> 7, sub = tid & 127;
        const int g = sub >> 3, cell = sub & 7;        // 16 pairs x 8 cells
        const int px = cell & 1, py = (cell >> 1) & 1, pz = cell >> 2;
        ull acc[1][8];
        #pragma unroll
        for (int j = 0; j < 8; j++) acc[0][j] = 0ull;
        #pragma unroll 1
        for (int k = 0; k < 4; k++) {
            const int ic = icg * 4 + k;
            float p[64];
            load_patch<4>(smem + BUF3_OFF + ic * 64, px, py, pz, p);
            conv_acc<1>(p, w4u + (g * 16 + ic) * 27, 0, acc);
        }
        ull* scr = (ull*)sB;
        #pragma unroll
        for (int j = 0; j < 8; j++) scr[(sub * 4 + icg) * 8 + j] = acc[0][j];
        __syncthreads();
        if (icg == 0) {                                // tid < 128 reduces
            float mlo = 0.0f, mhi = 0.0f;
            #pragma unroll
            for (int j = 0; j < 8; j++) {
                float lo = 0.0f, hi = 0.0f;
                #pragma unroll
                for (int q = 0; q < 4; q++) {
                    float a, c; unpk(scr[(sub * 4 + q) * 8 + j], a, c);
                    lo += a; hi += c;
                }
                if (j == 0) { mlo = lo; mhi = hi; }
                else        { mlo = fmaxf(mlo, lo); mhi = fmaxf(mhi, hi); }
            }
            const int oc0 = 2 * g;
            smem[BUF4_OFF + oc0 * 8 + cell]       = lrelu(mlo + __ldg(&b4[oc0]));
            smem[BUF4_OFF + (oc0 + 1) * 8 + cell] = lrelu(mhi + __ldg(&b4[oc0 + 1]));
        }
    }
    __syncthreads();

    // ---------------- stage 5: conv5 (32->64) @2^3 + pool -> feat[64] -----------
    // two 32-oc chunks; packed w5 pairs staged into region A (27648 floats)
    #pragma unroll 1
    for (int ch = 0; ch < 2; ch++) {
        float2* w5d = (float2*)sA;                     // [16 pairs][32 ic][27]
        for (int i = tid; i < 13824; i += NTH) {
            const int gl = i / 864, rem = i % 864, ic = rem / 27, t = rem % 27;
            const int o0 = ch * 32 + 2 * gl;
            w5d[i] = make_float2(w5[o0 * 864 + ic * 27 + t],
                                 w5[(o0 + 1) * 864 + ic * 27 + t]);
        }
        __syncthreads();
        const ull* w5u = (const ull*)sA;
        const int icg = tid >> 7, sub = tid & 127;     // 4 ic-groups of 8
        const int gl = sub >> 3, cell = sub & 7;       // 16 pairs x 8 conv pos
        const int dx = cell & 1, dy = (cell >> 1) & 1, dz = cell >> 2;
        ull acc = 0ull;
        #pragma unroll 1
        for (int k = 0; k < 8; k++) {
            const int ic = icg * 8 + k;
            const float* xin = smem + BUF4_OFF + ic * 8;
            const ull* wp = w5u + (gl * 32 + ic) * 27;
            #pragma unroll
            for (int j = 0; j < 8; j++) {
                const int jz = j >> 2, jy = (j >> 1) & 1, jx = j & 1;
                ffma2(acc, wp[((1 - dz + jz) * 3 + (1 - dy + jy)) * 3 + (1 - dx + jx)],
                      dup2(xin[j]));
            }
        }
        ull* scr = (ull*)sB;
        scr[sub * 4 + icg] = acc;
        __syncthreads();
        if (tid < 128) {
            float lo = 0.0f, hi = 0.0f;
            #pragma unroll
            for (int q = 0; q < 4; q++) {
                float a, c; unpk(scr[tid * 4 + q], a, c);
                lo += a; hi += c;
            }
            #pragma unroll
            for (int m = 1; m < 8; m <<= 1) {
                lo = fmaxf(lo, __shfl_xor_sync(0xffffffffu, lo, m));
                hi = fmaxf(hi, __shfl_xor_sync(0xffffffffu, hi, m));
            }
            if (cell == 0) {
                const int o0 = ch * 32 + 2 * gl;
                smem[FEAT_OFF + o0]     = lrelu(lo + __ldg(&b5[o0]));
                smem[FEAT_OFF + o0 + 1] = lrelu(hi + __ldg(&b5[o0 + 1]));
            }
        }
        __syncthreads();
    }

    // ---------------- heads: [64]->[6,32]->[6,16]->[6,4] -> normalize -----------
    if (tid < 192) {                                   // layer 1
        const int h = tid >> 5, o = tid & 31;
        float acc = __ldg(&hb1[h * 32 + o]);
        const float* Wp = hW1 + (h * 64) * 32 + o;
        #pragma unroll
        for (int f = 0; f < 64; f++) acc += smem[FEAT_OFF + f] * __ldg(&Wp[f * 32]);
        smem[HSCR_OFF + tid] = lrelu(acc);
    }
    __syncthreads();
    if (tid < 96) {                                    // layer 2
        const int h = tid >> 4, o = tid & 15;
        float acc = __ldg(&hb2[h * 16 + o]);
        const float* Wp  = hW2 + (h * 32) * 16 + o;
        const float* hin = smem + HSCR_OFF + h * 32;
        #pragma unroll
        for (int f = 0; f < 32; f++) acc += hin[f] * __ldg(&Wp[f * 16]);
        smem[HSCR_OFF + 192 + tid] = lrelu(acc);
    }
    __syncthreads();
    if (tid < 24) {                                    // layer 3
        const int h = tid >> 2, o = tid & 3;
        float acc = __ldg(&hb3[h * 4 + o]);
        const float* Wp  = hW3 + (h * 16) * 4 + o;
        const float* hin = smem + HSCR_OFF + 192 + h * 16;
        #pragma unroll
        for (int f = 0; f < 16; f++) acc += hin[f] * __ldg(&Wp[f * 4]);
        smem[HSCR_OFF + 288 + tid] = lrelu(acc);
    }
    __syncthreads();
    if (tid < 24) {                                    // unitize over 4-vector
        const int h = tid >> 2;
        const float* hv = smem + HSCR_OFF + 288 + h * 4;
        const float n = rsqrtf(hv[0] * hv[0] + hv[1] * hv[1] +
                               hv[2] * hv[2] + hv[3] * hv[3]);
        out[(size_t)b * 24 + tid] = smem[HSCR_OFF + 288 + tid] * n;
    }
}

extern "C" void kernel_launch(void* const* d_in, const int* in_sizes, int n_in,
                              void* d_out, int out_size)
{
    const int B = in_sizes[0] / 32768;                 // 1024
    const size_t smem_bytes = (size_t)SMEM_FLOATS * sizeof(float);  // 221088 B
    cudaFuncSetAttribute(prs_net_kernel,
                         cudaFuncAttributeMaxDynamicSharedMemorySize,
                         (int)smem_bytes);
    prs_net_kernel<<<B, NTH, smem_bytes>>>(
        (const float*)d_in[0],
        (const float*)d_in[1],  (const float*)d_in[2],
        (const float*)d_in[3],  (const float*)d_in[4],
        (const float*)d_in[5],  (const float*)d_in[6],
        (const float*)d_in[7],  (const float*)d_in[8],
        (const float*)d_in[9],  (const float*)d_in[10],
        (const float*)d_in[11], (const float*)d_in[12],
        (const float*)d_in[13], (const float*)d_in[14],
        (const float*)d_in[15], (const float*)d_in[16],
        (float*)d_out);
}